// round 1
// baseline (speedup 1.0000x reference)
#include <cuda_runtime.h>
#include <math.h>

#define B_  2
#define L_  2048
#define D_  1024
#define H_  16
#define HD_ 64
#define SCALE_ 0.125f  /* 64^-0.5 */

// Scratch (allocation-free rule: __device__ globals)
__device__ float g_q[(size_t)B_ * H_ * L_ * HD_];     // (B,H,L,HD)
__device__ float g_attn[(size_t)B_ * L_ * D_];        // (B,L,D) pre-projection

// ---------------------------------------------------------------------------
// Tiled SGEMM: C(M x NCOLS) = A(M x 1024) @ W(1024 x NCOLS) + bias
// BM=BN=128, BK=8, 256 threads, 8x8 register tile per thread.
// QKV=1: scatter into q/k/v (B,H,L,HD) layouts. QKV=0: plain row-major store.
// ---------------------------------------------------------------------------
template<int NCOLS, int QKV>
__global__ __launch_bounds__(256)
void gemm_kernel(const float* __restrict__ A, const float* __restrict__ W,
                 const float* __restrict__ bias,
                 float* __restrict__ d0, float* __restrict__ d1,
                 float* __restrict__ d2)
{
    __shared__ float As[8][128];   // transposed: As[k][m]
    __shared__ float Bs[8][128];   // Bs[k][n]

    const int m0 = blockIdx.y * 128;
    const int n0 = blockIdx.x * 128;
    const int tid = threadIdx.x;
    const int tx = tid & 15;       // n micro-tile: 8*tx
    const int ty = tid >> 4;       // m micro-tile: 8*ty

    const int ar = tid >> 1;          // 0..127
    const int ac = (tid & 1) * 4;     // 0 or 4
    const int br = tid >> 5;          // 0..7
    const int bc = (tid & 31) * 4;    // 0..124

    float acc[8][8];
#pragma unroll
    for (int i = 0; i < 8; i++)
#pragma unroll
        for (int j = 0; j < 8; j++) acc[i][j] = 0.f;

    for (int k0 = 0; k0 < D_; k0 += 8) {
        const float4 av = *reinterpret_cast<const float4*>(
            A + (size_t)(m0 + ar) * D_ + k0 + ac);
        const float4 bv = *reinterpret_cast<const float4*>(
            W + (size_t)(k0 + br) * NCOLS + n0 + bc);
        As[ac + 0][ar] = av.x; As[ac + 1][ar] = av.y;
        As[ac + 2][ar] = av.z; As[ac + 3][ar] = av.w;
        *reinterpret_cast<float4*>(&Bs[br][bc]) = bv;
        __syncthreads();

#pragma unroll
        for (int k = 0; k < 8; k++) {
            float a[8], b[8];
            *reinterpret_cast<float4*>(a)     = *reinterpret_cast<const float4*>(&As[k][ty * 8]);
            *reinterpret_cast<float4*>(a + 4) = *reinterpret_cast<const float4*>(&As[k][ty * 8 + 4]);
            *reinterpret_cast<float4*>(b)     = *reinterpret_cast<const float4*>(&Bs[k][tx * 8]);
            *reinterpret_cast<float4*>(b + 4) = *reinterpret_cast<const float4*>(&Bs[k][tx * 8 + 4]);
#pragma unroll
            for (int i = 0; i < 8; i++)
#pragma unroll
                for (int j = 0; j < 8; j++)
                    acc[i][j] = fmaf(a[i], b[j], acc[i][j]);
        }
        __syncthreads();
    }

    if (QKV) {
        // n = s*1024 + h*64 + d ; whole block shares one s (128 | 1024)
        const int s = n0 >> 10;
        float* dst = (s == 0) ? d0 : (s == 1) ? d1 : d2;
#pragma unroll
        for (int i = 0; i < 8; i++) {
            const int m = m0 + ty * 8 + i;
            const int bb = m >> 11;           // m / L_
            const int l  = m & (L_ - 1);
#pragma unroll
            for (int j = 0; j < 8; j++) {
                const int n = n0 + tx * 8 + j;
                const int h = (n >> 6) & (H_ - 1);
                const int d = n & (HD_ - 1);
                dst[(((size_t)(bb * H_ + h)) * L_ + l) * HD_ + d]
                    = acc[i][j] + bias[n];
            }
        }
    } else {
#pragma unroll
        for (int i = 0; i < 8; i++) {
            const int m = m0 + ty * 8 + i;
#pragma unroll
            for (int j = 0; j < 8; j++) {
                const int n = n0 + tx * 8 + j;
                d0[(size_t)m * NCOLS + n] = acc[i][j] + bias[n];
            }
        }
    }
}

// ---------------------------------------------------------------------------
// Flash attention (causal): per (b,h), Q tile 128 rows x key tiles of 64.
// 128 threads: ty in [0,16) owns 8 rows, tx in [0,8) owns 8 cols.
// Online softmax; P staged through SMEM for the P@V accumulation.
// Output written to g_attn in (B, L, H*HD) layout.
// ---------------------------------------------------------------------------
#define ATTN_SS 65
#define ATTN_SMEM ((128 + 64 + 64 + 128) * ATTN_SS * 4)

__global__ __launch_bounds__(128)
void attn_kernel(const float* __restrict__ qg, const float* __restrict__ kg,
                 const float* __restrict__ vg, float* __restrict__ og)
{
    extern __shared__ float sm[];
    float* Qs = sm;                    // 128 x ATTN_SS
    float* Ks = Qs + 128 * ATTN_SS;    //  64 x ATTN_SS
    float* Vs = Ks + 64 * ATTN_SS;     //  64 x ATTN_SS
    float* Ps = Vs + 64 * ATTN_SS;     // 128 x ATTN_SS

    const int t    = (int)gridDim.x - 1 - (int)blockIdx.x;  // heavy tiles first
    const int bh   = blockIdx.y;
    const int row0 = t * 128;
    const size_t base = (size_t)bh * L_ * HD_;
    const float* qp = qg + base;
    const float* kp = kg + base;
    const float* vp = vg + base;

    const int tid = threadIdx.x;
    const int tx = tid & 7;
    const int ty = tid >> 3;

    // Load Q tile 128x64 (float4 from gmem, scalar into padded smem)
    for (int i4 = tid; i4 < 128 * 16; i4 += 128) {
        const int r = i4 >> 4, c = (i4 & 15) * 4;
        const float4 v = *reinterpret_cast<const float4*>(
            qp + (size_t)(row0 + r) * HD_ + c);
        Qs[r * ATTN_SS + c + 0] = v.x; Qs[r * ATTN_SS + c + 1] = v.y;
        Qs[r * ATTN_SS + c + 2] = v.z; Qs[r * ATTN_SS + c + 3] = v.w;
    }

    float m_i[8], l_i[8], acc[8][8];
#pragma unroll
    for (int i = 0; i < 8; i++) {
        m_i[i] = -1e30f; l_i[i] = 0.f;
#pragma unroll
        for (int j = 0; j < 8; j++) acc[i][j] = 0.f;
    }
    __syncthreads();

    const int jmax = 2 * t + 1;   // keys up to 64*jmax+63 == row0+127
    for (int j0 = 0; j0 <= jmax; j0++) {
        const int c0 = j0 * 64;

        // Load K and V tiles 64x64
        for (int i4 = tid; i4 < 64 * 16; i4 += 128) {
            const int r = i4 >> 4, c = (i4 & 15) * 4;
            const float4 kv = *reinterpret_cast<const float4*>(
                kp + (size_t)(c0 + r) * HD_ + c);
            Ks[r * ATTN_SS + c + 0] = kv.x; Ks[r * ATTN_SS + c + 1] = kv.y;
            Ks[r * ATTN_SS + c + 2] = kv.z; Ks[r * ATTN_SS + c + 3] = kv.w;
            const float4 vv = *reinterpret_cast<const float4*>(
                vp + (size_t)(c0 + r) * HD_ + c);
            Vs[r * ATTN_SS + c + 0] = vv.x; Vs[r * ATTN_SS + c + 1] = vv.y;
            Vs[r * ATTN_SS + c + 2] = vv.z; Vs[r * ATTN_SS + c + 3] = vv.w;
        }
        __syncthreads();

        // S = Q @ K^T  (128x64 tile; this thread: 8x8)
        float s[8][8];
#pragma unroll
        for (int i = 0; i < 8; i++)
#pragma unroll
            for (int j = 0; j < 8; j++) s[i][j] = 0.f;

#pragma unroll 4
        for (int d = 0; d < 64; d++) {
            float a[8], b[8];
#pragma unroll
            for (int i = 0; i < 8; i++) a[i] = Qs[(ty * 8 + i) * ATTN_SS + d];
#pragma unroll
            for (int j = 0; j < 8; j++) b[j] = Ks[(tx * 8 + j) * ATTN_SS + d];
#pragma unroll
            for (int i = 0; i < 8; i++)
#pragma unroll
                for (int j = 0; j < 8; j++)
                    s[i][j] = fmaf(a[i], b[j], s[i][j]);
        }

        // Scale + causal mask (only tiles that straddle the diagonal)
        const bool dm = (c0 + 63 > row0);
#pragma unroll
        for (int i = 0; i < 8; i++) {
            const int row = row0 + ty * 8 + i;
#pragma unroll
            for (int j = 0; j < 8; j++) {
                s[i][j] *= SCALE_;
                if (dm && (c0 + tx * 8 + j > row)) s[i][j] = -1e30f;
            }
        }

        // Online softmax update per row (row group = 8 lanes, same ty)
#pragma unroll
        for (int i = 0; i < 8; i++) {
            float mx = s[i][0];
#pragma unroll
            for (int j = 1; j < 8; j++) mx = fmaxf(mx, s[i][j]);
#pragma unroll
            for (int off = 4; off > 0; off >>= 1)
                mx = fmaxf(mx, __shfl_xor_sync(0xffffffffu, mx, off, 8));
            const float mn = fmaxf(m_i[i], mx);
            const float corr = __expf(m_i[i] - mn);
            m_i[i] = mn;
            float ls = 0.f;
#pragma unroll
            for (int j = 0; j < 8; j++) {
                s[i][j] = __expf(s[i][j] - mn);
                ls += s[i][j];
            }
#pragma unroll
            for (int off = 4; off > 0; off >>= 1)
                ls += __shfl_xor_sync(0xffffffffu, ls, off, 8);
            l_i[i] = l_i[i] * corr + ls;
#pragma unroll
            for (int j = 0; j < 8; j++) acc[i][j] *= corr;
        }

        // Stage P
#pragma unroll
        for (int i = 0; i < 8; i++)
#pragma unroll
            for (int j = 0; j < 8; j++)
                Ps[(ty * 8 + i) * ATTN_SS + tx * 8 + j] = s[i][j];
        __syncthreads();

        // O += P @ V   (128x64 += 128x64 @ 64x64)
#pragma unroll 4
        for (int c = 0; c < 64; c++) {
            float pa[8], vb[8];
#pragma unroll
            for (int i = 0; i < 8; i++) pa[i] = Ps[(ty * 8 + i) * ATTN_SS + c];
#pragma unroll
            for (int j = 0; j < 8; j++) vb[j] = Vs[c * ATTN_SS + tx * 8 + j];
#pragma unroll
            for (int i = 0; i < 8; i++)
#pragma unroll
                for (int j = 0; j < 8; j++)
                    acc[i][j] = fmaf(pa[i], vb[j], acc[i][j]);
        }
        __syncthreads();
    }

    // Finalize: divide by l, write (B, L, H*HD)
    const int bb = bh >> 4;
    const int h  = bh & (H_ - 1);
#pragma unroll
    for (int i = 0; i < 8; i++) {
        const int l = row0 + ty * 8 + i;
        const float inv = 1.0f / l_i[i];
#pragma unroll
        for (int j = 0; j < 8; j++) {
            og[((size_t)(bb * L_ + l)) * D_ + h * HD_ + tx * 8 + j]
                = acc[i][j] * inv;
        }
    }
}

// ---------------------------------------------------------------------------
extern "C" void kernel_launch(void* const* d_in, const int* in_sizes, int n_in,
                              void* d_out, int out_size)
{
    const float* x     = (const float*)d_in[0];
    const float* w_qkv = (const float*)d_in[1];
    const float* b_qkv = (const float*)d_in[2];
    const float* w_out = (const float*)d_in[3];
    const float* b_out = (const float*)d_in[4];

    float* out  = (float*)d_out;                                   // (B,L,D)
    float* kout = out  + (size_t)B_ * L_ * D_;                     // (B,H,L,HD)
    float* vout = kout + (size_t)B_ * H_ * L_ * HD_;               // (B,H,L,HD)

    float* qbuf = nullptr;
    float* abuf = nullptr;
    cudaGetSymbolAddress((void**)&qbuf, g_q);
    cudaGetSymbolAddress((void**)&abuf, g_attn);

    cudaFuncSetAttribute(attn_kernel,
                         cudaFuncAttributeMaxDynamicSharedMemorySize, ATTN_SMEM);

    // 1) QKV projection + scatter to (B,H,L,HD)
    gemm_kernel<3 * D_, 1><<<dim3((3 * D_) / 128, (B_ * L_) / 128), 256>>>(
        x, w_qkv, b_qkv, qbuf, kout, vout);

    // 2) Causal flash attention -> g_attn (B,L,D)
    attn_kernel<<<dim3(L_ / 128, B_ * H_), 128, ATTN_SMEM>>>(
        qbuf, kout, vout, abuf);

    // 3) Output projection
    gemm_kernel<D_, 0><<<dim3(D_ / 128, (B_ * L_) / 128), 256>>>(
        abuf, w_out, b_out, out, nullptr, nullptr);
}

// round 4
// speedup vs baseline: 1.2725x; 1.2725x over previous
#include <cuda_runtime.h>
#include <cstdint>
#include <math.h>

#define B_  2
#define L_  2048
#define D_  1024
#define H_  16
#define HD_ 64
#define SCALE_ 0.125f  /* 64^-0.5 */

// Scratch (allocation-free rule: __device__ globals)
__device__ float g_q[(size_t)B_ * H_ * L_ * HD_];     // (B,H,L,HD)
__device__ float g_attn[(size_t)B_ * L_ * D_];        // (B,L,D) pre-projection

// ===========================================================================
// Portable (sm_80+) PTX helpers: cp.async + mma.sync tf32
// ===========================================================================
__device__ __forceinline__ uint32_t smem_u32(const void* p) {
    uint32_t a;
    asm("{ .reg .u64 t; cvta.to.shared.u64 t, %1; cvt.u32.u64 %0, t; }"
        : "=r"(a) : "l"(p));
    return a;
}

__device__ __forceinline__ void cp_async16(uint32_t dst, const void* src) {
    asm volatile("cp.async.cg.shared.global [%0], [%1], 16;"
                 :: "r"(dst), "l"(src) : "memory");
}
__device__ __forceinline__ void cp_commit() {
    asm volatile("cp.async.commit_group;" ::: "memory");
}
template<int N>
__device__ __forceinline__ void cp_wait() {
    asm volatile("cp.async.wait_group %0;" :: "n"(N) : "memory");
}

// 3xTF32 split: x = hi + lo, each tf32-representable (RN)
__device__ __forceinline__ void tf32_split(float x, uint32_t& hi, uint32_t& lo) {
    asm("cvt.rna.tf32.f32 %0, %1;" : "=r"(hi) : "f"(x));
    const float r = x - __uint_as_float(hi);
    asm("cvt.rna.tf32.f32 %0, %1;" : "=r"(lo) : "f"(r));
}

// D(16x8,f32) += A(16x8,tf32) @ B(8x8,tf32)
#define MMA_TF32(c, a, b)                                                      \
    asm volatile(                                                              \
        "mma.sync.aligned.m16n8k8.row.col.f32.tf32.tf32.f32 "                  \
        "{%0,%1,%2,%3}, {%4,%5,%6,%7}, {%8,%9}, {%0,%1,%2,%3};"                \
        : "+f"((c)[0]), "+f"((c)[1]), "+f"((c)[2]), "+f"((c)[3])               \
        : "r"((a)[0]), "r"((a)[1]), "r"((a)[2]), "r"((a)[3]),                  \
          "r"((b)[0]), "r"((b)[1]))

// ===========================================================================
// tf32x3 mma.sync GEMM: C(M x NCOLS) = A(M x 1024) @ W(1024 x NCOLS) + bias
// CTA tile 128x128, K slab 32, double-buffered cp.async. 256 threads,
// 8 warps in 2(m) x 4(n), warp tile 64x32, per-thread acc 4x4x4 fp32.
// Each product computed as hi*hi + hi*lo + lo*hi (fp32-accurate).
// QKV=1: scatter into q/k/v (B,H,L,HD). QKV=0: row-major store.
// ===========================================================================
#define AST 36                       // A smem row stride (floats): bank = 4g+t
#define BST 136                      // B smem row stride (floats): bank = 8t+g
#define A_FLOATS (128 * AST)         // 4608
#define B_FLOATS (32 * BST)          // 4352
#define GEMM_SMEM ((2 * A_FLOATS + 2 * B_FLOATS) * 4)   // 71680 B

template<int NCOLS, int QKV>
__global__ __launch_bounds__(256)
void gemm_mma(const float* __restrict__ A, const float* __restrict__ W,
              const float* __restrict__ bias,
              float* __restrict__ d0, float* __restrict__ d1,
              float* __restrict__ d2)
{
    extern __shared__ float smf[];
    float* Abuf[2] = { smf, smf + A_FLOATS };
    float* Bbuf[2] = { smf + 2 * A_FLOATS, smf + 2 * A_FLOATS + B_FLOATS };
    const uint32_t sb = smem_u32(smf);
    const uint32_t sA[2] = { sb, sb + A_FLOATS * 4 };
    const uint32_t sB[2] = { sb + 2 * A_FLOATS * 4,
                             sb + (2 * A_FLOATS + B_FLOATS) * 4 };

    const int tid  = threadIdx.x;
    const int wid  = tid >> 5;
    const int lane = tid & 31;
    const int g = lane >> 2;          // 0..7
    const int t = lane & 3;           // 0..3
    const int wm0 = (wid >> 2) * 64;  // warp m origin in CTA tile
    const int wn0 = (wid & 3) * 32;   // warp n origin
    const int m0 = blockIdx.y * 128;
    const int n0 = blockIdx.x * 128;

    float acc[4][4][4];
#pragma unroll
    for (int mt = 0; mt < 4; mt++)
#pragma unroll
        for (int nt = 0; nt < 4; nt++)
#pragma unroll
            for (int r = 0; r < 4; r++) acc[mt][nt][r] = 0.f;

    // ---- stage loader (cp.async, raw fp32; split to tf32 pairs at use) ----
    auto load_stage = [&](int s, int b) {
        const int k0 = s * 32;
        const float* ap = A + (size_t)m0 * D_ + k0;
#pragma unroll
        for (int i = 0; i < 4; i++) {
            const int idx = tid + i * 256;      // 1024 float4: 128r x 8c4
            const int r = idx >> 3, c4 = idx & 7;
            cp_async16(sA[b] + (uint32_t)(r * AST + c4 * 4) * 4,
                       ap + (size_t)r * D_ + c4 * 4);
        }
        const float* wp = W + (size_t)k0 * NCOLS + n0;
#pragma unroll
        for (int i = 0; i < 4; i++) {
            const int idx = tid + i * 256;      // 1024 float4: 32k x 32n4
            const int k = idx >> 5, n4 = idx & 31;
            cp_async16(sB[b] + (uint32_t)(k * BST + n4 * 4) * 4,
                       wp + (size_t)k * NCOLS + n4 * 4);
        }
        cp_commit();
    };

    // ---- per-stage compute: 128x128 += 128x32 @ 32x128 (tf32x3) ----
    auto compute_stage = [&](int b) {
        const float* Ab = Abuf[b];
        const float* Bb = Bbuf[b];
#pragma unroll
        for (int k8 = 0; k8 < 4; k8++) {
            const int kb = k8 * 8;
            uint32_t ah[4][4], al[4][4], bh[4][2], bl[4][2];
#pragma unroll
            for (int mt = 0; mt < 4; mt++) {
                const float* p  = Ab + (wm0 + mt * 16 + g) * AST + kb;
                const float* p2 = p + 8 * AST;
                tf32_split(p[t],      ah[mt][0], al[mt][0]);
                tf32_split(p2[t],     ah[mt][1], al[mt][1]);
                tf32_split(p[t + 4],  ah[mt][2], al[mt][2]);
                tf32_split(p2[t + 4], ah[mt][3], al[mt][3]);
            }
#pragma unroll
            for (int nt = 0; nt < 4; nt++) {
                const int nn = wn0 + nt * 8 + g;
                tf32_split(Bb[(kb + t) * BST + nn],     bh[nt][0], bl[nt][0]);
                tf32_split(Bb[(kb + t + 4) * BST + nn], bh[nt][1], bl[nt][1]);
            }
#pragma unroll
            for (int mt = 0; mt < 4; mt++)
#pragma unroll
                for (int nt = 0; nt < 4; nt++) {
                    MMA_TF32(acc[mt][nt], al[mt], bh[nt]);  // lo*hi
                    MMA_TF32(acc[mt][nt], ah[mt], bl[nt]);  // hi*lo
                    MMA_TF32(acc[mt][nt], ah[mt], bh[nt]);  // hi*hi (largest last)
                }
        }
    };

    // ---- pipelined main loop (32 K-slabs) ----
    load_stage(0, 0);
    constexpr int NS = D_ / 32;
    for (int s = 0; s < NS; s++) {
        const int b = s & 1;
        if (s + 1 < NS) {
            load_stage(s + 1, b ^ 1);
            cp_wait<1>();
        } else {
            cp_wait<0>();
        }
        __syncthreads();
        compute_stage(b);
        __syncthreads();
    }

    // ---- epilogue: fragment layout -> gmem, +bias, optional qkv scatter ----
#pragma unroll
    for (int mt = 0; mt < 4; mt++) {
#pragma unroll
        for (int half = 0; half < 2; half++) {
            const int m = m0 + wm0 + mt * 16 + g + half * 8;
            int bb = 0, l = 0;
            if (QKV) { bb = m >> 11; l = m & (L_ - 1); }
#pragma unroll
            for (int nt = 0; nt < 4; nt++) {
                const int n = n0 + wn0 + nt * 8 + t * 2;
                float2 v;
                v.x = acc[mt][nt][half * 2 + 0] + bias[n];
                v.y = acc[mt][nt][half * 2 + 1] + bias[n + 1];
                if (QKV) {
                    const int sidx = n0 >> 10;  // block-uniform: q/k/v select
                    float* dst = (sidx == 0) ? d0 : (sidx == 1) ? d1 : d2;
                    const int h = (n >> 6) & (H_ - 1), dd = n & (HD_ - 1);
                    *reinterpret_cast<float2*>(
                        dst + (((size_t)(bb * H_ + h)) * L_ + l) * HD_ + dd) = v;
                } else {
                    *reinterpret_cast<float2*>(d0 + (size_t)m * NCOLS + n) = v;
                }
            }
        }
    }
}

// ---------------------------------------------------------------------------
// Flash attention (causal), unchanged from round 1 (validated).
// ---------------------------------------------------------------------------
#define ATTN_SS 65
#define ATTN_SMEM ((128 + 64 + 64 + 128) * ATTN_SS * 4)

__global__ __launch_bounds__(128)
void attn_kernel(const float* __restrict__ qg, const float* __restrict__ kg,
                 const float* __restrict__ vg, float* __restrict__ og)
{
    extern __shared__ float smf[];
    float* Qs = smf;                   // 128 x ATTN_SS
    float* Ks = Qs + 128 * ATTN_SS;    //  64 x ATTN_SS
    float* Vs = Ks + 64 * ATTN_SS;     //  64 x ATTN_SS
    float* Ps = Vs + 64 * ATTN_SS;     // 128 x ATTN_SS

    const int t    = (int)gridDim.x - 1 - (int)blockIdx.x;  // heavy tiles first
    const int bh   = blockIdx.y;
    const int row0 = t * 128;
    const size_t base = (size_t)bh * L_ * HD_;
    const float* qp = qg + base;
    const float* kp = kg + base;
    const float* vp = vg + base;

    const int tid = threadIdx.x;
    const int tx = tid & 7;
    const int ty = tid >> 3;

    for (int i4 = tid; i4 < 128 * 16; i4 += 128) {
        const int r = i4 >> 4, c = (i4 & 15) * 4;
        const float4 v = *reinterpret_cast<const float4*>(
            qp + (size_t)(row0 + r) * HD_ + c);
        Qs[r * ATTN_SS + c + 0] = v.x; Qs[r * ATTN_SS + c + 1] = v.y;
        Qs[r * ATTN_SS + c + 2] = v.z; Qs[r * ATTN_SS + c + 3] = v.w;
    }

    float m_i[8], l_i[8], acc[8][8];
#pragma unroll
    for (int i = 0; i < 8; i++) {
        m_i[i] = -1e30f; l_i[i] = 0.f;
#pragma unroll
        for (int j = 0; j < 8; j++) acc[i][j] = 0.f;
    }
    __syncthreads();

    const int jmax = 2 * t + 1;
    for (int j0 = 0; j0 <= jmax; j0++) {
        const int c0 = j0 * 64;

        for (int i4 = tid; i4 < 64 * 16; i4 += 128) {
            const int r = i4 >> 4, c = (i4 & 15) * 4;
            const float4 kv = *reinterpret_cast<const float4*>(
                kp + (size_t)(c0 + r) * HD_ + c);
            Ks[r * ATTN_SS + c + 0] = kv.x; Ks[r * ATTN_SS + c + 1] = kv.y;
            Ks[r * ATTN_SS + c + 2] = kv.z; Ks[r * ATTN_SS + c + 3] = kv.w;
            const float4 vv = *reinterpret_cast<const float4*>(
                vp + (size_t)(c0 + r) * HD_ + c);
            Vs[r * ATTN_SS + c + 0] = vv.x; Vs[r * ATTN_SS + c + 1] = vv.y;
            Vs[r * ATTN_SS + c + 2] = vv.z; Vs[r * ATTN_SS + c + 3] = vv.w;
        }
        __syncthreads();

        float s[8][8];
#pragma unroll
        for (int i = 0; i < 8; i++)
#pragma unroll
            for (int j = 0; j < 8; j++) s[i][j] = 0.f;

#pragma unroll 4
        for (int d = 0; d < 64; d++) {
            float a[8], b[8];
#pragma unroll
            for (int i = 0; i < 8; i++) a[i] = Qs[(ty * 8 + i) * ATTN_SS + d];
#pragma unroll
            for (int j = 0; j < 8; j++) b[j] = Ks[(tx * 8 + j) * ATTN_SS + d];
#pragma unroll
            for (int i = 0; i < 8; i++)
#pragma unroll
                for (int j = 0; j < 8; j++)
                    s[i][j] = fmaf(a[i], b[j], s[i][j]);
        }

        const bool dm = (c0 + 63 > row0);
#pragma unroll
        for (int i = 0; i < 8; i++) {
            const int row = row0 + ty * 8 + i;
#pragma unroll
            for (int j = 0; j < 8; j++) {
                s[i][j] *= SCALE_;
                if (dm && (c0 + tx * 8 + j > row)) s[i][j] = -1e30f;
            }
        }

#pragma unroll
        for (int i = 0; i < 8; i++) {
            float mx = s[i][0];
#pragma unroll
            for (int j = 1; j < 8; j++) mx = fmaxf(mx, s[i][j]);
#pragma unroll
            for (int off = 4; off > 0; off >>= 1)
                mx = fmaxf(mx, __shfl_xor_sync(0xffffffffu, mx, off, 8));
            const float mn = fmaxf(m_i[i], mx);
            const float corr = __expf(m_i[i] - mn);
            m_i[i] = mn;
            float ls = 0.f;
#pragma unroll
            for (int j = 0; j < 8; j++) {
                s[i][j] = __expf(s[i][j] - mn);
                ls += s[i][j];
            }
#pragma unroll
            for (int off = 4; off > 0; off >>= 1)
                ls += __shfl_xor_sync(0xffffffffu, ls, off, 8);
            l_i[i] = l_i[i] * corr + ls;
#pragma unroll
            for (int j = 0; j < 8; j++) acc[i][j] *= corr;
        }

#pragma unroll
        for (int i = 0; i < 8; i++)
#pragma unroll
            for (int j = 0; j < 8; j++)
                Ps[(ty * 8 + i) * ATTN_SS + tx * 8 + j] = s[i][j];
        __syncthreads();

#pragma unroll 4
        for (int c = 0; c < 64; c++) {
            float pa[8], vb[8];
#pragma unroll
            for (int i = 0; i < 8; i++) pa[i] = Ps[(ty * 8 + i) * ATTN_SS + c];
#pragma unroll
            for (int j = 0; j < 8; j++) vb[j] = Vs[c * ATTN_SS + tx * 8 + j];
#pragma unroll
            for (int i = 0; i < 8; i++)
#pragma unroll
                for (int j = 0; j < 8; j++)
                    acc[i][j] = fmaf(pa[i], vb[j], acc[i][j]);
        }
        __syncthreads();
    }

    const int bb = bh >> 4;
    const int h  = bh & (H_ - 1);
#pragma unroll
    for (int i = 0; i < 8; i++) {
        const int l = row0 + ty * 8 + i;
        const float inv = 1.0f / l_i[i];
#pragma unroll
        for (int j = 0; j < 8; j++) {
            og[((size_t)(bb * L_ + l)) * D_ + h * HD_ + tx * 8 + j]
                = acc[i][j] * inv;
        }
    }
}

// ---------------------------------------------------------------------------
extern "C" void kernel_launch(void* const* d_in, const int* in_sizes, int n_in,
                              void* d_out, int out_size)
{
    const float* x     = (const float*)d_in[0];
    const float* w_qkv = (const float*)d_in[1];
    const float* b_qkv = (const float*)d_in[2];
    const float* w_out = (const float*)d_in[3];
    const float* b_out = (const float*)d_in[4];

    float* out  = (float*)d_out;                                   // (B,L,D)
    float* kout = out  + (size_t)B_ * L_ * D_;                     // (B,H,L,HD)
    float* vout = kout + (size_t)B_ * H_ * L_ * HD_;               // (B,H,L,HD)

    float* qbuf = nullptr;
    float* abuf = nullptr;
    cudaGetSymbolAddress((void**)&qbuf, g_q);
    cudaGetSymbolAddress((void**)&abuf, g_attn);

    cudaFuncSetAttribute(gemm_mma<3 * D_, 1>,
                         cudaFuncAttributeMaxDynamicSharedMemorySize, GEMM_SMEM);
    cudaFuncSetAttribute(gemm_mma<D_, 0>,
                         cudaFuncAttributeMaxDynamicSharedMemorySize, GEMM_SMEM);
    cudaFuncSetAttribute(attn_kernel,
                         cudaFuncAttributeMaxDynamicSharedMemorySize, ATTN_SMEM);

    // 1) QKV projection (tf32x3 mma.sync) + scatter to (B,H,L,HD)
    gemm_mma<3 * D_, 1><<<dim3((3 * D_) / 128, (B_ * L_) / 128), 256, GEMM_SMEM>>>(
        x, w_qkv, b_qkv, qbuf, kout, vout);

    // 2) Causal flash attention -> g_attn (B,L,D)
    attn_kernel<<<dim3(L_ / 128, B_ * H_), 128, ATTN_SMEM>>>(
        qbuf, kout, vout, abuf);

    // 3) Output projection (tf32x3 mma.sync)
    gemm_mma<D_, 0><<<dim3(D_ / 128, (B_ * L_) / 128), 256, GEMM_SMEM>>>(
        abuf, w_out, b_out, out, nullptr, nullptr);
}

// round 5
// speedup vs baseline: 1.5473x; 1.2160x over previous
#include <cuda_runtime.h>
#include <cstdint>
#include <math.h>

#define B_  2
#define L_  2048
#define D_  1024
#define H_  16
#define HD_ 64
#define SCALE_ 0.125f  /* 64^-0.5 */

// Scratch (allocation-free rule: __device__ globals)
__device__ float g_q[(size_t)B_ * H_ * L_ * HD_];     // (B,H,L,HD)
__device__ float g_attn[(size_t)B_ * L_ * D_];        // (B,L,D) pre-projection

// ===========================================================================
// Portable (sm_80+) PTX helpers: cp.async + mma.sync tf32
// ===========================================================================
__device__ __forceinline__ uint32_t smem_u32(const void* p) {
    uint32_t a;
    asm("{ .reg .u64 t; cvta.to.shared.u64 t, %1; cvt.u32.u64 %0, t; }"
        : "=r"(a) : "l"(p));
    return a;
}

__device__ __forceinline__ void cp_async16(uint32_t dst, const void* src) {
    asm volatile("cp.async.cg.shared.global [%0], [%1], 16;"
                 :: "r"(dst), "l"(src) : "memory");
}
__device__ __forceinline__ void cp_commit() {
    asm volatile("cp.async.commit_group;" ::: "memory");
}
template<int N>
__device__ __forceinline__ void cp_wait() {
    asm volatile("cp.async.wait_group %0;" :: "n"(N) : "memory");
}

// 3xTF32 split: x = hi + lo, each tf32-representable (RN)
__device__ __forceinline__ void tf32_split(float x, uint32_t& hi, uint32_t& lo) {
    asm("cvt.rna.tf32.f32 %0, %1;" : "=r"(hi) : "f"(x));
    const float r = x - __uint_as_float(hi);
    asm("cvt.rna.tf32.f32 %0, %1;" : "=r"(lo) : "f"(r));
}

// D(16x8,f32) += A(16x8,tf32) @ B(8x8,tf32)
#define MMA_TF32(c, a, b)                                                      \
    asm volatile(                                                              \
        "mma.sync.aligned.m16n8k8.row.col.f32.tf32.tf32.f32 "                  \
        "{%0,%1,%2,%3}, {%4,%5,%6,%7}, {%8,%9}, {%0,%1,%2,%3};"                \
        : "+f"((c)[0]), "+f"((c)[1]), "+f"((c)[2]), "+f"((c)[3])               \
        : "r"((a)[0]), "r"((a)[1]), "r"((a)[2]), "r"((a)[3]),                  \
          "r"((b)[0]), "r"((b)[1]))

// ===========================================================================
// tf32x3 mma.sync GEMM (unchanged from round 4, validated)
// ===========================================================================
#define AST 36
#define BST 136
#define A_FLOATS (128 * AST)
#define B_FLOATS (32 * BST)
#define GEMM_SMEM ((2 * A_FLOATS + 2 * B_FLOATS) * 4)

template<int NCOLS, int QKV>
__global__ __launch_bounds__(256)
void gemm_mma(const float* __restrict__ A, const float* __restrict__ W,
              const float* __restrict__ bias,
              float* __restrict__ d0, float* __restrict__ d1,
              float* __restrict__ d2)
{
    extern __shared__ float smf[];
    float* Abuf[2] = { smf, smf + A_FLOATS };
    float* Bbuf[2] = { smf + 2 * A_FLOATS, smf + 2 * A_FLOATS + B_FLOATS };
    const uint32_t sb = smem_u32(smf);
    const uint32_t sA[2] = { sb, sb + A_FLOATS * 4 };
    const uint32_t sB[2] = { sb + 2 * A_FLOATS * 4,
                             sb + (2 * A_FLOATS + B_FLOATS) * 4 };

    const int tid  = threadIdx.x;
    const int wid  = tid >> 5;
    const int lane = tid & 31;
    const int g = lane >> 2;
    const int t = lane & 3;
    const int wm0 = (wid >> 2) * 64;
    const int wn0 = (wid & 3) * 32;
    const int m0 = blockIdx.y * 128;
    const int n0 = blockIdx.x * 128;

    float acc[4][4][4];
#pragma unroll
    for (int mt = 0; mt < 4; mt++)
#pragma unroll
        for (int nt = 0; nt < 4; nt++)
#pragma unroll
            for (int r = 0; r < 4; r++) acc[mt][nt][r] = 0.f;

    auto load_stage = [&](int s, int b) {
        const int k0 = s * 32;
        const float* ap = A + (size_t)m0 * D_ + k0;
#pragma unroll
        for (int i = 0; i < 4; i++) {
            const int idx = tid + i * 256;
            const int r = idx >> 3, c4 = idx & 7;
            cp_async16(sA[b] + (uint32_t)(r * AST + c4 * 4) * 4,
                       ap + (size_t)r * D_ + c4 * 4);
        }
        const float* wp = W + (size_t)k0 * NCOLS + n0;
#pragma unroll
        for (int i = 0; i < 4; i++) {
            const int idx = tid + i * 256;
            const int k = idx >> 5, n4 = idx & 31;
            cp_async16(sB[b] + (uint32_t)(k * BST + n4 * 4) * 4,
                       wp + (size_t)k * NCOLS + n4 * 4);
        }
        cp_commit();
    };

    auto compute_stage = [&](int b) {
        const float* Ab = Abuf[b];
        const float* Bb = Bbuf[b];
#pragma unroll
        for (int k8 = 0; k8 < 4; k8++) {
            const int kb = k8 * 8;
            uint32_t ah[4][4], al[4][4], bh[4][2], bl[4][2];
#pragma unroll
            for (int mt = 0; mt < 4; mt++) {
                const float* p  = Ab + (wm0 + mt * 16 + g) * AST + kb;
                const float* p2 = p + 8 * AST;
                tf32_split(p[t],      ah[mt][0], al[mt][0]);
                tf32_split(p2[t],     ah[mt][1], al[mt][1]);
                tf32_split(p[t + 4],  ah[mt][2], al[mt][2]);
                tf32_split(p2[t + 4], ah[mt][3], al[mt][3]);
            }
#pragma unroll
            for (int nt = 0; nt < 4; nt++) {
                const int nn = wn0 + nt * 8 + g;
                tf32_split(Bb[(kb + t) * BST + nn],     bh[nt][0], bl[nt][0]);
                tf32_split(Bb[(kb + t + 4) * BST + nn], bh[nt][1], bl[nt][1]);
            }
#pragma unroll
            for (int mt = 0; mt < 4; mt++)
#pragma unroll
                for (int nt = 0; nt < 4; nt++) {
                    MMA_TF32(acc[mt][nt], al[mt], bh[nt]);
                    MMA_TF32(acc[mt][nt], ah[mt], bl[nt]);
                    MMA_TF32(acc[mt][nt], ah[mt], bh[nt]);
                }
        }
    };

    load_stage(0, 0);
    constexpr int NS = D_ / 32;
    for (int s = 0; s < NS; s++) {
        const int b = s & 1;
        if (s + 1 < NS) {
            load_stage(s + 1, b ^ 1);
            cp_wait<1>();
        } else {
            cp_wait<0>();
        }
        __syncthreads();
        compute_stage(b);
        __syncthreads();
    }

#pragma unroll
    for (int mt = 0; mt < 4; mt++) {
#pragma unroll
        for (int half = 0; half < 2; half++) {
            const int m = m0 + wm0 + mt * 16 + g + half * 8;
            int bb = 0, l = 0;
            if (QKV) { bb = m >> 11; l = m & (L_ - 1); }
#pragma unroll
            for (int nt = 0; nt < 4; nt++) {
                const int n = n0 + wn0 + nt * 8 + t * 2;
                float2 v;
                v.x = acc[mt][nt][half * 2 + 0] + bias[n];
                v.y = acc[mt][nt][half * 2 + 1] + bias[n + 1];
                if (QKV) {
                    const int sidx = n0 >> 10;
                    float* dst = (sidx == 0) ? d0 : (sidx == 1) ? d1 : d2;
                    const int h = (n >> 6) & (H_ - 1), dd = n & (HD_ - 1);
                    *reinterpret_cast<float2*>(
                        dst + (((size_t)(bb * H_ + h)) * L_ + l) * HD_ + dd) = v;
                } else {
                    *reinterpret_cast<float2*>(d0 + (size_t)m * NCOLS + n) = v;
                }
            }
        }
    }
}

// ===========================================================================
// Flash attention (causal) with tf32x3 mma.sync.
// 256 threads / 8 warps; warp w owns q-rows [w*16, w*16+16) of a 128-row tile.
// Key tiles of 64. Q pre-split to hi/lo SMEM once; K/V cp.async'd raw then
// pre-split once per tile (shared by all warps). P split in-register.
// ===========================================================================
#define QST 68
#define KST 68
#define VST 72
#define PST 68
#define OFF_QHI 0
#define OFF_QLO (128 * QST)                 // 8704
#define OFF_KHI (2 * 128 * QST)             // 17408
#define OFF_KLO (OFF_KHI + 64 * KST)        // 21760
#define OFF_VHI (OFF_KLO + 64 * KST)        // 26112
#define OFF_VLO (OFF_VHI + 64 * VST)        // 30720
#define OFF_PS  (OFF_VLO + 64 * VST)        // 35328
#define OFF_KRAW (OFF_PS + 128 * PST)       // 44032
#define OFF_VRAW (OFF_KRAW + 64 * 64)       // 48128
#define ATTN_FLOATS (OFF_VRAW + 64 * 64)    // 52224
#define ATTN2_SMEM (ATTN_FLOATS * 4)        // 208896

__global__ __launch_bounds__(256)
void attn_mma(const float* __restrict__ qg, const float* __restrict__ kg,
              const float* __restrict__ vg, float* __restrict__ og)
{
    extern __shared__ float sm[];
    float* Qhi = sm + OFF_QHI;
    float* Qlo = sm + OFF_QLO;
    float* Khi = sm + OFF_KHI;
    float* Klo = sm + OFF_KLO;
    float* Vhi = sm + OFF_VHI;
    float* Vlo = sm + OFF_VLO;
    float* Ps  = sm + OFF_PS;
    float* Kraw = sm + OFF_KRAW;
    float* Vraw = sm + OFF_VRAW;
    const uint32_t sKraw = smem_u32(Kraw);
    const uint32_t sVraw = smem_u32(Vraw);

    const int tidx = (int)gridDim.x - 1 - (int)blockIdx.x;  // heavy tiles first
    const int bh   = blockIdx.y;
    const int row0 = tidx * 128;
    const size_t base = (size_t)bh * L_ * HD_;
    const float* qp = qg + base;
    const float* kp = kg + base;
    const float* vp = vg + base;

    const int tid = threadIdx.x;
    const int wid = tid >> 5;
    const int lane = tid & 31;
    const int g = lane >> 2;
    const int t = lane & 3;
    const int wrow = wid * 16;

    // ---- load + split Q tile (128x64) once ----
#pragma unroll
    for (int i = 0; i < 8; i++) {
        const int idx = tid + i * 256;          // 2048 float4
        const int r = idx >> 4, c = (idx & 15) * 4;
        const float4 v = *reinterpret_cast<const float4*>(
            qp + (size_t)(row0 + r) * HD_ + c);
#pragma unroll
        for (int e = 0; e < 4; e++) {
            const float f = (e == 0) ? v.x : (e == 1) ? v.y : (e == 2) ? v.z : v.w;
            uint32_t hi, lo;
            tf32_split(f, hi, lo);
            Qhi[r * QST + c + e] = __uint_as_float(hi);
            Qlo[r * QST + c + e] = __uint_as_float(lo);
        }
    }

    float accO[8][4];
    float m_i[2] = { -1e30f, -1e30f };
    float l_i[2] = { 0.f, 0.f };
#pragma unroll
    for (int nt = 0; nt < 8; nt++)
#pragma unroll
        for (int e = 0; e < 4; e++) accO[nt][e] = 0.f;

    // ---- K/V raw tile prefetch (cp.async) ----
    auto load_kv = [&](int c0) {
#pragma unroll
        for (int i = 0; i < 4; i++) {
            const int idx = tid + i * 256;      // 1024 float4
            const int r = idx >> 4, c = (idx & 15) * 4;
            cp_async16(sKraw + (uint32_t)(r * 64 + c) * 4,
                       kp + (size_t)(c0 + r) * HD_ + c);
            cp_async16(sVraw + (uint32_t)(r * 64 + c) * 4,
                       vp + (size_t)(c0 + r) * HD_ + c);
        }
        cp_commit();
    };
    load_kv(0);

    const int jmax = 2 * tidx + 1;
    for (int j0 = 0; j0 <= jmax; j0++) {
        const int c0 = j0 * 64;

        cp_wait<0>();
        __syncthreads();   // raw tile ready AND all warps done with prior hi/lo

        // ---- split K/V raw -> hi/lo planes (shared work, once per tile) ----
#pragma unroll
        for (int i = 0; i < 4; i++) {
            const int idx = tid + i * 256;
            const int r = idx >> 4, c = (idx & 15) * 4;
            const float4 kv = *reinterpret_cast<const float4*>(&Kraw[r * 64 + c]);
            const float4 vv = *reinterpret_cast<const float4*>(&Vraw[r * 64 + c]);
#pragma unroll
            for (int e = 0; e < 4; e++) {
                const float fk = (e == 0) ? kv.x : (e == 1) ? kv.y : (e == 2) ? kv.z : kv.w;
                const float fv = (e == 0) ? vv.x : (e == 1) ? vv.y : (e == 2) ? vv.z : vv.w;
                uint32_t hi, lo;
                tf32_split(fk, hi, lo);
                Khi[r * KST + c + e] = __uint_as_float(hi);
                Klo[r * KST + c + e] = __uint_as_float(lo);
                tf32_split(fv, hi, lo);
                Vhi[r * VST + c + e] = __uint_as_float(hi);
                Vlo[r * VST + c + e] = __uint_as_float(lo);
            }
        }
        __syncthreads();

        if (j0 < jmax) load_kv(c0 + 64);   // overlap next raw load with compute

        // ---- S = Q @ K^T (warp: 16 rows x 64 cols), tf32x3 ----
        float s[8][4];
#pragma unroll
        for (int nt = 0; nt < 8; nt++)
#pragma unroll
            for (int e = 0; e < 4; e++) s[nt][e] = 0.f;

#pragma unroll
        for (int k8 = 0; k8 < 8; k8++) {
            const int kb = k8 * 8;
            uint32_t ah[4], al[4];
            const float* q0h = Qhi + (wrow + g) * QST + kb;
            const float* q1h = q0h + 8 * QST;
            const float* q0l = Qlo + (wrow + g) * QST + kb;
            const float* q1l = q0l + 8 * QST;
            ah[0] = __float_as_uint(q0h[t]);     al[0] = __float_as_uint(q0l[t]);
            ah[1] = __float_as_uint(q1h[t]);     al[1] = __float_as_uint(q1l[t]);
            ah[2] = __float_as_uint(q0h[t + 4]); al[2] = __float_as_uint(q0l[t + 4]);
            ah[3] = __float_as_uint(q1h[t + 4]); al[3] = __float_as_uint(q1l[t + 4]);
#pragma unroll
            for (int nt = 0; nt < 8; nt++) {
                const int nn = nt * 8 + g;
                uint32_t bh2[2], bl2[2];
                bh2[0] = __float_as_uint(Khi[nn * KST + kb + t]);
                bh2[1] = __float_as_uint(Khi[nn * KST + kb + t + 4]);
                bl2[0] = __float_as_uint(Klo[nn * KST + kb + t]);
                bl2[1] = __float_as_uint(Klo[nn * KST + kb + t + 4]);
                MMA_TF32(s[nt], al, bh2);
                MMA_TF32(s[nt], ah, bl2);
                MMA_TF32(s[nt], ah, bh2);
            }
        }

        // ---- scale + causal mask ----
        const bool dm = (c0 + 63 > row0);
        const int r0 = row0 + wrow + g;
        const int r1 = r0 + 8;
#pragma unroll
        for (int nt = 0; nt < 8; nt++) {
#pragma unroll
            for (int e = 0; e < 4; e++) {
                const int col = c0 + nt * 8 + 2 * t + (e & 1);
                const int row = (e < 2) ? r0 : r1;
                s[nt][e] *= SCALE_;
                if (dm && col > row) s[nt][e] = -1e30f;
            }
        }

        // ---- online softmax (rows r0, r1; quad = 4 lanes) ----
        float mx0 = -1e30f, mx1 = -1e30f;
#pragma unroll
        for (int nt = 0; nt < 8; nt++) {
            mx0 = fmaxf(mx0, fmaxf(s[nt][0], s[nt][1]));
            mx1 = fmaxf(mx1, fmaxf(s[nt][2], s[nt][3]));
        }
#pragma unroll
        for (int off = 1; off <= 2; off <<= 1) {
            mx0 = fmaxf(mx0, __shfl_xor_sync(0xffffffffu, mx0, off));
            mx1 = fmaxf(mx1, __shfl_xor_sync(0xffffffffu, mx1, off));
        }
        const float mn0 = fmaxf(m_i[0], mx0);
        const float mn1 = fmaxf(m_i[1], mx1);
        const float corr0 = __expf(m_i[0] - mn0);
        const float corr1 = __expf(m_i[1] - mn1);
        m_i[0] = mn0; m_i[1] = mn1;

        float ls0 = 0.f, ls1 = 0.f;
#pragma unroll
        for (int nt = 0; nt < 8; nt++) {
            s[nt][0] = __expf(s[nt][0] - mn0);
            s[nt][1] = __expf(s[nt][1] - mn0);
            s[nt][2] = __expf(s[nt][2] - mn1);
            s[nt][3] = __expf(s[nt][3] - mn1);
            ls0 += s[nt][0] + s[nt][1];
            ls1 += s[nt][2] + s[nt][3];
        }
#pragma unroll
        for (int off = 1; off <= 2; off <<= 1) {
            ls0 += __shfl_xor_sync(0xffffffffu, ls0, off);
            ls1 += __shfl_xor_sync(0xffffffffu, ls1, off);
        }
        l_i[0] = l_i[0] * corr0 + ls0;
        l_i[1] = l_i[1] * corr1 + ls1;
#pragma unroll
        for (int nt = 0; nt < 8; nt++) {
            accO[nt][0] *= corr0; accO[nt][1] *= corr0;
            accO[nt][2] *= corr1; accO[nt][3] *= corr1;
        }

        // ---- stage P to warp-private SMEM rows ----
#pragma unroll
        for (int nt = 0; nt < 8; nt++) {
            Ps[(wrow + g) * PST + nt * 8 + 2 * t]         = s[nt][0];
            Ps[(wrow + g) * PST + nt * 8 + 2 * t + 1]     = s[nt][1];
            Ps[(wrow + g + 8) * PST + nt * 8 + 2 * t]     = s[nt][2];
            Ps[(wrow + g + 8) * PST + nt * 8 + 2 * t + 1] = s[nt][3];
        }
        __syncwarp();

        // ---- O += P @ V (warp: 16 x 64 += 16 x 64 @ 64 x 64), tf32x3 ----
#pragma unroll
        for (int k8 = 0; k8 < 8; k8++) {
            const int kb = k8 * 8;
            uint32_t ph[4], pl[4];
            tf32_split(Ps[(wrow + g) * PST + kb + t],         ph[0], pl[0]);
            tf32_split(Ps[(wrow + g + 8) * PST + kb + t],     ph[1], pl[1]);
            tf32_split(Ps[(wrow + g) * PST + kb + t + 4],     ph[2], pl[2]);
            tf32_split(Ps[(wrow + g + 8) * PST + kb + t + 4], ph[3], pl[3]);
#pragma unroll
            for (int nt = 0; nt < 8; nt++) {
                const int nn = nt * 8 + g;
                uint32_t vh[2], vl[2];
                vh[0] = __float_as_uint(Vhi[(kb + t) * VST + nn]);
                vh[1] = __float_as_uint(Vhi[(kb + t + 4) * VST + nn]);
                vl[0] = __float_as_uint(Vlo[(kb + t) * VST + nn]);
                vl[1] = __float_as_uint(Vlo[(kb + t + 4) * VST + nn]);
                MMA_TF32(accO[nt], pl, vh);
                MMA_TF32(accO[nt], ph, vl);
                MMA_TF32(accO[nt], ph, vh);
            }
        }
    }

    // ---- finalize: /l, write (B, L, H*HD) ----
    const int bb = bh >> 4;
    const int h  = bh & (H_ - 1);
    const float inv0 = 1.0f / l_i[0];
    const float inv1 = 1.0f / l_i[1];
    const int r0 = row0 + wrow + g;
#pragma unroll
    for (int nt = 0; nt < 8; nt++) {
        const int col = h * HD_ + nt * 8 + 2 * t;
        float2 v0 = { accO[nt][0] * inv0, accO[nt][1] * inv0 };
        float2 v1 = { accO[nt][2] * inv1, accO[nt][3] * inv1 };
        *reinterpret_cast<float2*>(og + ((size_t)(bb * L_ + r0)) * D_ + col) = v0;
        *reinterpret_cast<float2*>(og + ((size_t)(bb * L_ + r0 + 8)) * D_ + col) = v1;
    }
}

// ---------------------------------------------------------------------------
extern "C" void kernel_launch(void* const* d_in, const int* in_sizes, int n_in,
                              void* d_out, int out_size)
{
    const float* x     = (const float*)d_in[0];
    const float* w_qkv = (const float*)d_in[1];
    const float* b_qkv = (const float*)d_in[2];
    const float* w_out = (const float*)d_in[3];
    const float* b_out = (const float*)d_in[4];

    float* out  = (float*)d_out;                                   // (B,L,D)
    float* kout = out  + (size_t)B_ * L_ * D_;                     // (B,H,L,HD)
    float* vout = kout + (size_t)B_ * H_ * L_ * HD_;               // (B,H,L,HD)

    float* qbuf = nullptr;
    float* abuf = nullptr;
    cudaGetSymbolAddress((void**)&qbuf, g_q);
    cudaGetSymbolAddress((void**)&abuf, g_attn);

    cudaFuncSetAttribute(gemm_mma<3 * D_, 1>,
                         cudaFuncAttributeMaxDynamicSharedMemorySize, GEMM_SMEM);
    cudaFuncSetAttribute(gemm_mma<D_, 0>,
                         cudaFuncAttributeMaxDynamicSharedMemorySize, GEMM_SMEM);
    cudaFuncSetAttribute(attn_mma,
                         cudaFuncAttributeMaxDynamicSharedMemorySize, ATTN2_SMEM);

    // 1) QKV projection (tf32x3 mma.sync) + scatter to (B,H,L,HD)
    gemm_mma<3 * D_, 1><<<dim3((3 * D_) / 128, (B_ * L_) / 128), 256, GEMM_SMEM>>>(
        x, w_qkv, b_qkv, qbuf, kout, vout);

    // 2) Causal flash attention (tf32x3 mma.sync) -> g_attn (B,L,D)
    attn_mma<<<dim3(L_ / 128, B_ * H_), 256, ATTN2_SMEM>>>(
        qbuf, kout, vout, abuf);

    // 3) Output projection (tf32x3 mma.sync)
    gemm_mma<D_, 0><<<dim3(D_ / 128, (B_ * L_) / 128), 256, GEMM_SMEM>>>(
        abuf, w_out, b_out, out, nullptr, nullptr);
}

// round 6
// speedup vs baseline: 1.6661x; 1.0768x over previous
#include <cuda_runtime.h>
#include <cstdint>
#include <math.h>

#define B_  2
#define L_  2048
#define D_  1024
#define H_  16
#define HD_ 64
#define SCALE_ 0.125f  /* 64^-0.5 */

#define NQKV ((size_t)B_ * H_ * L_ * HD_)   // 4,194,304
#define NX   ((size_t)B_ * L_ * D_)         // 4,194,304
#define NWQ  ((size_t)D_ * 3 * D_)          // 3,145,728
#define NWO  ((size_t)D_ * D_)              // 1,048,576

// Scratch (allocation-free rule: __device__ globals) — hi/lo tf32 planes
__device__ float g_xhi[NX],  g_xlo[NX];
__device__ float g_wqh[NWQ], g_wql[NWQ];
__device__ float g_woh[NWO], g_wol[NWO];
__device__ float g_qhi[NQKV], g_qlo[NQKV];
__device__ float g_khi[NQKV], g_klo[NQKV];
__device__ float g_vhi[NQKV], g_vlo[NQKV];
__device__ float g_ahi[NX],  g_alo[NX];

// ===========================================================================
// PTX helpers
// ===========================================================================
__device__ __forceinline__ uint32_t smem_u32(const void* p) {
    uint32_t a;
    asm("{ .reg .u64 t; cvta.to.shared.u64 t, %1; cvt.u32.u64 %0, t; }"
        : "=r"(a) : "l"(p));
    return a;
}
__device__ __forceinline__ void cp_async16(uint32_t dst, const void* src) {
    asm volatile("cp.async.cg.shared.global [%0], [%1], 16;"
                 :: "r"(dst), "l"(src) : "memory");
}
__device__ __forceinline__ void cp_commit() {
    asm volatile("cp.async.commit_group;" ::: "memory");
}
template<int N>
__device__ __forceinline__ void cp_wait() {
    asm volatile("cp.async.wait_group %0;" :: "n"(N) : "memory");
}
__device__ __forceinline__ void tf32_split(float x, uint32_t& hi, uint32_t& lo) {
    asm("cvt.rna.tf32.f32 %0, %1;" : "=r"(hi) : "f"(x));
    const float r = x - __uint_as_float(hi);
    asm("cvt.rna.tf32.f32 %0, %1;" : "=r"(lo) : "f"(r));
}
#define MMA_TF32(c, a, b)                                                      \
    asm volatile(                                                              \
        "mma.sync.aligned.m16n8k8.row.col.f32.tf32.tf32.f32 "                  \
        "{%0,%1,%2,%3}, {%4,%5,%6,%7}, {%8,%9}, {%0,%1,%2,%3};"                \
        : "+f"((c)[0]), "+f"((c)[1]), "+f"((c)[2]), "+f"((c)[3])               \
        : "r"((a)[0]), "r"((a)[1]), "r"((a)[2]), "r"((a)[3]),                  \
          "r"((b)[0]), "r"((b)[1]))

// ===========================================================================
// Elementwise tf32 hi/lo split prep kernel (float4 vectorized)
// ===========================================================================
__global__ __launch_bounds__(256)
void split_kernel(const float4* __restrict__ src, float4* __restrict__ hi,
                  float4* __restrict__ lo, int n4)
{
    const int i = blockIdx.x * blockDim.x + threadIdx.x;
    if (i >= n4) return;
    const float4 v = src[i];
    uint32_t h0, l0, h1, l1, h2, l2, h3, l3;
    tf32_split(v.x, h0, l0); tf32_split(v.y, h1, l1);
    tf32_split(v.z, h2, l2); tf32_split(v.w, h3, l3);
    float4 hv = { __uint_as_float(h0), __uint_as_float(h1),
                  __uint_as_float(h2), __uint_as_float(h3) };
    float4 lv = { __uint_as_float(l0), __uint_as_float(l1),
                  __uint_as_float(l2), __uint_as_float(l3) };
    hi[i] = hv;
    lo[i] = lv;
}

// ===========================================================================
// tf32x3 GEMM on pre-split planes: C = A @ W + bias
// CTA tile 128x128, K slab 32, double-buffered 4-plane cp.async. 256 threads.
// Inner loop: LDS + MMA only (no splits).
// QKV=1 epilogue: q -> hi/lo planes; k,v -> raw d_out + hi/lo planes.
// ===========================================================================
#define AST 36
#define BST 136
#define G_AF (128 * AST)                       // 4608
#define G_BF (32 * BST)                        // 4352
#define G_BUFSZ (2 * G_AF + 2 * G_BF)          // 17920 floats per buffer
#define GEMM_SMEM (2 * G_BUFSZ * 4)            // 143360 B

template<int NCOLS, int QKV>
__global__ __launch_bounds__(256)
void gemm_mma(const float* __restrict__ Ahi, const float* __restrict__ Alo,
              const float* __restrict__ Whi, const float* __restrict__ Wlo,
              const float* __restrict__ bias,
              float* __restrict__ o0, float* __restrict__ o1,
              float* __restrict__ o2, float* __restrict__ o3,
              float* __restrict__ o4, float* __restrict__ o5,
              float* __restrict__ o6, float* __restrict__ o7)
{
    extern __shared__ float smf[];
    const uint32_t sb = smem_u32(smf);

    const int tid  = threadIdx.x;
    const int wid  = tid >> 5;
    const int lane = tid & 31;
    const int g = lane >> 2;
    const int t = lane & 3;
    const int wm0 = (wid >> 2) * 64;
    const int wn0 = (wid & 3) * 32;
    const int m0 = blockIdx.y * 128;
    const int n0 = blockIdx.x * 128;

    float acc[4][4][4];
#pragma unroll
    for (int mt = 0; mt < 4; mt++)
#pragma unroll
        for (int nt = 0; nt < 4; nt++)
#pragma unroll
            for (int r = 0; r < 4; r++) acc[mt][nt][r] = 0.f;

    auto load_stage = [&](int s, int b) {
        const int k0 = s * 32;
        const uint32_t aH = sb + (uint32_t)(b * G_BUFSZ) * 4;
        const uint32_t aL = aH + G_AF * 4;
        const uint32_t bH = aL + G_AF * 4;
        const uint32_t bL = bH + G_BF * 4;
        const size_t abase = (size_t)m0 * D_ + k0;
#pragma unroll
        for (int i = 0; i < 4; i++) {
            const int idx = tid + i * 256;
            const int r = idx >> 3, c4 = idx & 7;
            const size_t go = abase + (size_t)r * D_ + c4 * 4;
            const uint32_t so = (uint32_t)(r * AST + c4 * 4) * 4;
            cp_async16(aH + so, Ahi + go);
            cp_async16(aL + so, Alo + go);
        }
        const size_t wbase = (size_t)k0 * NCOLS + n0;
#pragma unroll
        for (int i = 0; i < 4; i++) {
            const int idx = tid + i * 256;
            const int k = idx >> 5, n4 = idx & 31;
            const size_t go = wbase + (size_t)k * NCOLS + n4 * 4;
            const uint32_t so = (uint32_t)(k * BST + n4 * 4) * 4;
            cp_async16(bH + so, Whi + go);
            cp_async16(bL + so, Wlo + go);
        }
        cp_commit();
    };

    auto compute_stage = [&](int b) {
        const float* AH = smf + b * G_BUFSZ;
        const float* AL = AH + G_AF;
        const float* BH = AL + G_AF;
        const float* BL = BH + G_BF;
#pragma unroll
        for (int k8 = 0; k8 < 4; k8++) {
            const int kb = k8 * 8;
            uint32_t ah[4][4], al[4][4], bh[4][2], bl[4][2];
#pragma unroll
            for (int mt = 0; mt < 4; mt++) {
                const int ro = (wm0 + mt * 16 + g) * AST + kb;
                ah[mt][0] = __float_as_uint(AH[ro + t]);
                ah[mt][1] = __float_as_uint(AH[ro + 8 * AST + t]);
                ah[mt][2] = __float_as_uint(AH[ro + t + 4]);
                ah[mt][3] = __float_as_uint(AH[ro + 8 * AST + t + 4]);
                al[mt][0] = __float_as_uint(AL[ro + t]);
                al[mt][1] = __float_as_uint(AL[ro + 8 * AST + t]);
                al[mt][2] = __float_as_uint(AL[ro + t + 4]);
                al[mt][3] = __float_as_uint(AL[ro + 8 * AST + t + 4]);
            }
#pragma unroll
            for (int nt = 0; nt < 4; nt++) {
                const int nn = wn0 + nt * 8 + g;
                bh[nt][0] = __float_as_uint(BH[(kb + t) * BST + nn]);
                bh[nt][1] = __float_as_uint(BH[(kb + t + 4) * BST + nn]);
                bl[nt][0] = __float_as_uint(BL[(kb + t) * BST + nn]);
                bl[nt][1] = __float_as_uint(BL[(kb + t + 4) * BST + nn]);
            }
#pragma unroll
            for (int mt = 0; mt < 4; mt++)
#pragma unroll
                for (int nt = 0; nt < 4; nt++) {
                    MMA_TF32(acc[mt][nt], al[mt], bh[nt]);
                    MMA_TF32(acc[mt][nt], ah[mt], bl[nt]);
                    MMA_TF32(acc[mt][nt], ah[mt], bh[nt]);
                }
        }
    };

    load_stage(0, 0);
    constexpr int NS = D_ / 32;
    for (int s = 0; s < NS; s++) {
        const int b = s & 1;
        if (s + 1 < NS) {
            load_stage(s + 1, b ^ 1);
            cp_wait<1>();
        } else {
            cp_wait<0>();
        }
        __syncthreads();
        compute_stage(b);
        __syncthreads();
    }

    // epilogue
#pragma unroll
    for (int mt = 0; mt < 4; mt++) {
#pragma unroll
        for (int half = 0; half < 2; half++) {
            const int m = m0 + wm0 + mt * 16 + g + half * 8;
            int bb = 0, l = 0;
            if (QKV) { bb = m >> 11; l = m & (L_ - 1); }
#pragma unroll
            for (int nt = 0; nt < 4; nt++) {
                const int n = n0 + wn0 + nt * 8 + t * 2;
                float2 v;
                v.x = acc[mt][nt][half * 2 + 0] + bias[n];
                v.y = acc[mt][nt][half * 2 + 1] + bias[n + 1];
                if (QKV) {
                    const int sidx = n0 >> 10;  // block-uniform q/k/v select
                    const int h = (n >> 6) & (H_ - 1), dd = n & (HD_ - 1);
                    const size_t off =
                        (((size_t)(bb * H_ + h)) * L_ + l) * HD_ + dd;
                    uint32_t hx, lx, hy, ly;
                    tf32_split(v.x, hx, lx);
                    tf32_split(v.y, hy, ly);
                    float2 vh = { __uint_as_float(hx), __uint_as_float(hy) };
                    float2 vl = { __uint_as_float(lx), __uint_as_float(ly) };
                    if (sidx == 0) {
                        *reinterpret_cast<float2*>(o0 + off) = vh;  // qhi
                        *reinterpret_cast<float2*>(o1 + off) = vl;  // qlo
                    } else if (sidx == 1) {
                        *reinterpret_cast<float2*>(o6 + off) = v;   // k raw
                        *reinterpret_cast<float2*>(o2 + off) = vh;  // khi
                        *reinterpret_cast<float2*>(o3 + off) = vl;  // klo
                    } else {
                        *reinterpret_cast<float2*>(o7 + off) = v;   // v raw
                        *reinterpret_cast<float2*>(o4 + off) = vh;  // vhi
                        *reinterpret_cast<float2*>(o5 + off) = vl;  // vlo
                    }
                } else {
                    *reinterpret_cast<float2*>(o0 + (size_t)m * NCOLS + n) = v;
                }
            }
        }
    }
}

// ===========================================================================
// Flash attention (causal), tf32x3 mma on pre-split planes.
// 256 threads / 8 warps; warp w owns 16 q-rows of a 128-row tile; key tiles
// of 64, double-buffered cp.async of 4 K/V planes. P staging aliases the
// spent K planes of the active buffer. Output written pre-split (hi/lo).
// ===========================================================================
#define AQST 68
#define AKST 68
#define AVST 72
#define A_OFF_QLO  8704                     // 128*68
#define A_BUF0     17408
#define A_BUFSZ    17920                    // KHI 4352 + KLO 4352 + VHI 4608 + VLO 4608
#define ATTN_FLOATS (A_BUF0 + 2 * A_BUFSZ)  // 53248
#define ATTN_SMEM (ATTN_FLOATS * 4)         // 212992 B

__global__ __launch_bounds__(256)
void attn_mma(const float* __restrict__ qhi_g, const float* __restrict__ qlo_g,
              const float* __restrict__ khi_g, const float* __restrict__ klo_g,
              const float* __restrict__ vhi_g, const float* __restrict__ vlo_g,
              float* __restrict__ ahi_g, float* __restrict__ alo_g)
{
    extern __shared__ float sm[];
    const uint32_t sbase = smem_u32(sm);

    const int tidx = (int)gridDim.x - 1 - (int)blockIdx.x;  // heavy tiles first
    const int bh   = blockIdx.y;
    const int row0 = tidx * 128;
    const size_t base = (size_t)bh * L_ * HD_;
    const float* qph = qhi_g + base;
    const float* qpl = qlo_g + base;
    const float* kph = khi_g + base;
    const float* kpl = klo_g + base;
    const float* vph = vhi_g + base;
    const float* vpl = vlo_g + base;

    const int tid = threadIdx.x;
    const int wid = tid >> 5;
    const int lane = tid & 31;
    const int g = lane >> 2;
    const int t = lane & 3;
    const int wrow = wid * 16;

    // ---- load Q hi/lo planes (128x64) once ----
    float* Qhi = sm;
    float* Qlo = sm + A_OFF_QLO;
#pragma unroll
    for (int i = 0; i < 8; i++) {
        const int idx = tid + i * 256;          // 2048 float4
        const int r = idx >> 4, c = (idx & 15) * 4;
        const size_t go = (size_t)(row0 + r) * HD_ + c;
        *reinterpret_cast<float4*>(&Qhi[r * AQST + c]) =
            *reinterpret_cast<const float4*>(qph + go);
        *reinterpret_cast<float4*>(&Qlo[r * AQST + c]) =
            *reinterpret_cast<const float4*>(qpl + go);
    }

    float accO[8][4];
    float m_i[2] = { -1e30f, -1e30f };
    float l_i[2] = { 0.f, 0.f };
#pragma unroll
    for (int nt = 0; nt < 8; nt++)
#pragma unroll
        for (int e = 0; e < 4; e++) accO[nt][e] = 0.f;

    auto load_kv = [&](int c0, int b) {
        const uint32_t kH = sbase + (uint32_t)(A_BUF0 + b * A_BUFSZ) * 4;
        const uint32_t kL = kH + 4352 * 4;
        const uint32_t vH = kH + 8704 * 4;
        const uint32_t vL = kH + 13312 * 4;
#pragma unroll
        for (int i = 0; i < 4; i++) {
            const int idx = tid + i * 256;      // 1024 float4
            const int r = idx >> 4, c = (idx & 15) * 4;
            const size_t go = (size_t)(c0 + r) * HD_ + c;
            cp_async16(kH + (uint32_t)(r * AKST + c) * 4, kph + go);
            cp_async16(kL + (uint32_t)(r * AKST + c) * 4, kpl + go);
            cp_async16(vH + (uint32_t)(r * AVST + c) * 4, vph + go);
            cp_async16(vL + (uint32_t)(r * AVST + c) * 4, vpl + go);
        }
        cp_commit();
    };
    load_kv(0, 0);

    const int jmax = 2 * tidx + 1;
    for (int j0 = 0; j0 <= jmax; j0++) {
        const int c0 = j0 * 64;
        const int b = j0 & 1;

        cp_wait<0>();
        __syncthreads();   // buffer b ready; all warps done with prior tile

        if (j0 < jmax) load_kv(c0 + 64, b ^ 1);  // overlap with compute

        const float* Khi = sm + A_BUF0 + b * A_BUFSZ;
        const float* Klo = Khi + 4352;
        const float* Vhi = Khi + 8704;
        const float* Vlo = Khi + 13312;
        float* Ps = const_cast<float*>(Khi);     // aliased after mid-sync

        // ---- S = Q @ K^T (warp: 16 x 64), tf32x3 ----
        float s[8][4];
#pragma unroll
        for (int nt = 0; nt < 8; nt++)
#pragma unroll
            for (int e = 0; e < 4; e++) s[nt][e] = 0.f;

#pragma unroll
        for (int k8 = 0; k8 < 8; k8++) {
            const int kb = k8 * 8;
            uint32_t ah[4], al[4];
            const int qo = (wrow + g) * AQST + kb;
            ah[0] = __float_as_uint(Qhi[qo + t]);
            ah[1] = __float_as_uint(Qhi[qo + 8 * AQST + t]);
            ah[2] = __float_as_uint(Qhi[qo + t + 4]);
            ah[3] = __float_as_uint(Qhi[qo + 8 * AQST + t + 4]);
            al[0] = __float_as_uint(Qlo[qo + t]);
            al[1] = __float_as_uint(Qlo[qo + 8 * AQST + t]);
            al[2] = __float_as_uint(Qlo[qo + t + 4]);
            al[3] = __float_as_uint(Qlo[qo + 8 * AQST + t + 4]);
#pragma unroll
            for (int nt = 0; nt < 8; nt++) {
                const int nn = nt * 8 + g;
                uint32_t bh2[2], bl2[2];
                bh2[0] = __float_as_uint(Khi[nn * AKST + kb + t]);
                bh2[1] = __float_as_uint(Khi[nn * AKST + kb + t + 4]);
                bl2[0] = __float_as_uint(Klo[nn * AKST + kb + t]);
                bl2[1] = __float_as_uint(Klo[nn * AKST + kb + t + 4]);
                MMA_TF32(s[nt], al, bh2);
                MMA_TF32(s[nt], ah, bl2);
                MMA_TF32(s[nt], ah, bh2);
            }
        }

        // ---- scale + causal mask ----
        const bool dm = (c0 + 63 > row0);
        const int r0 = row0 + wrow + g;
        const int r1 = r0 + 8;
#pragma unroll
        for (int nt = 0; nt < 8; nt++) {
#pragma unroll
            for (int e = 0; e < 4; e++) {
                const int col = c0 + nt * 8 + 2 * t + (e & 1);
                const int row = (e < 2) ? r0 : r1;
                s[nt][e] *= SCALE_;
                if (dm && col > row) s[nt][e] = -1e30f;
            }
        }

        // ---- online softmax (rows r0, r1; quad = 4 lanes) ----
        float mx0 = -1e30f, mx1 = -1e30f;
#pragma unroll
        for (int nt = 0; nt < 8; nt++) {
            mx0 = fmaxf(mx0, fmaxf(s[nt][0], s[nt][1]));
            mx1 = fmaxf(mx1, fmaxf(s[nt][2], s[nt][3]));
        }
#pragma unroll
        for (int off = 1; off <= 2; off <<= 1) {
            mx0 = fmaxf(mx0, __shfl_xor_sync(0xffffffffu, mx0, off));
            mx1 = fmaxf(mx1, __shfl_xor_sync(0xffffffffu, mx1, off));
        }
        const float mn0 = fmaxf(m_i[0], mx0);
        const float mn1 = fmaxf(m_i[1], mx1);
        const float corr0 = __expf(m_i[0] - mn0);
        const float corr1 = __expf(m_i[1] - mn1);
        m_i[0] = mn0; m_i[1] = mn1;

        float ls0 = 0.f, ls1 = 0.f;
#pragma unroll
        for (int nt = 0; nt < 8; nt++) {
            s[nt][0] = __expf(s[nt][0] - mn0);
            s[nt][1] = __expf(s[nt][1] - mn0);
            s[nt][2] = __expf(s[nt][2] - mn1);
            s[nt][3] = __expf(s[nt][3] - mn1);
            ls0 += s[nt][0] + s[nt][1];
            ls1 += s[nt][2] + s[nt][3];
        }
#pragma unroll
        for (int off = 1; off <= 2; off <<= 1) {
            ls0 += __shfl_xor_sync(0xffffffffu, ls0, off);
            ls1 += __shfl_xor_sync(0xffffffffu, ls1, off);
        }
        l_i[0] = l_i[0] * corr0 + ls0;
        l_i[1] = l_i[1] * corr1 + ls1;
#pragma unroll
        for (int nt = 0; nt < 8; nt++) {
            accO[nt][0] *= corr0; accO[nt][1] *= corr0;
            accO[nt][2] *= corr1; accO[nt][3] *= corr1;
        }

        __syncthreads();   // all warps done reading K[b] before P overwrites it

        // ---- stage P into aliased K region (warp-private rows) ----
#pragma unroll
        for (int nt = 0; nt < 8; nt++) {
            Ps[(wrow + g) * AQST + nt * 8 + 2 * t]         = s[nt][0];
            Ps[(wrow + g) * AQST + nt * 8 + 2 * t + 1]     = s[nt][1];
            Ps[(wrow + g + 8) * AQST + nt * 8 + 2 * t]     = s[nt][2];
            Ps[(wrow + g + 8) * AQST + nt * 8 + 2 * t + 1] = s[nt][3];
        }
        __syncwarp();

        // ---- O += P @ V, tf32x3 (P split in-register) ----
#pragma unroll
        for (int k8 = 0; k8 < 8; k8++) {
            const int kb = k8 * 8;
            uint32_t ph[4], pl[4];
            tf32_split(Ps[(wrow + g) * AQST + kb + t],         ph[0], pl[0]);
            tf32_split(Ps[(wrow + g + 8) * AQST + kb + t],     ph[1], pl[1]);
            tf32_split(Ps[(wrow + g) * AQST + kb + t + 4],     ph[2], pl[2]);
            tf32_split(Ps[(wrow + g + 8) * AQST + kb + t + 4], ph[3], pl[3]);
#pragma unroll
            for (int nt = 0; nt < 8; nt++) {
                const int nn = nt * 8 + g;
                uint32_t vh[2], vl[2];
                vh[0] = __float_as_uint(Vhi[(kb + t) * AVST + nn]);
                vh[1] = __float_as_uint(Vhi[(kb + t + 4) * AVST + nn]);
                vl[0] = __float_as_uint(Vlo[(kb + t) * AVST + nn]);
                vl[1] = __float_as_uint(Vlo[(kb + t + 4) * AVST + nn]);
                MMA_TF32(accO[nt], pl, vh);
                MMA_TF32(accO[nt], ph, vl);
                MMA_TF32(accO[nt], ph, vh);
            }
        }
    }

    // ---- finalize: /l, write pre-split hi/lo in (B, L, H*HD) ----
    const int bb = bh >> 4;
    const int h  = bh & (H_ - 1);
    const float inv0 = 1.0f / l_i[0];
    const float inv1 = 1.0f / l_i[1];
    const int r0 = row0 + wrow + g;
#pragma unroll
    for (int nt = 0; nt < 8; nt++) {
        const int col = h * HD_ + nt * 8 + 2 * t;
        const size_t o0 = ((size_t)(bb * L_ + r0)) * D_ + col;
        const size_t o1 = ((size_t)(bb * L_ + r0 + 8)) * D_ + col;
        uint32_t hx, lx, hy, ly;
        tf32_split(accO[nt][0] * inv0, hx, lx);
        tf32_split(accO[nt][1] * inv0, hy, ly);
        *reinterpret_cast<float2*>(ahi_g + o0) =
            { __uint_as_float(hx), __uint_as_float(hy) };
        *reinterpret_cast<float2*>(alo_g + o0) =
            { __uint_as_float(lx), __uint_as_float(ly) };
        tf32_split(accO[nt][2] * inv1, hx, lx);
        tf32_split(accO[nt][3] * inv1, hy, ly);
        *reinterpret_cast<float2*>(ahi_g + o1) =
            { __uint_as_float(hx), __uint_as_float(hy) };
        *reinterpret_cast<float2*>(alo_g + o1) =
            { __uint_as_float(lx), __uint_as_float(ly) };
    }
}

// ---------------------------------------------------------------------------
extern "C" void kernel_launch(void* const* d_in, const int* in_sizes, int n_in,
                              void* d_out, int out_size)
{
    const float* x     = (const float*)d_in[0];
    const float* w_qkv = (const float*)d_in[1];
    const float* b_qkv = (const float*)d_in[2];
    const float* w_out = (const float*)d_in[3];
    const float* b_out = (const float*)d_in[4];

    float* out  = (float*)d_out;                                   // (B,L,D)
    float* kout = out  + (size_t)B_ * L_ * D_;                     // (B,H,L,HD)
    float* vout = kout + (size_t)B_ * H_ * L_ * HD_;               // (B,H,L,HD)

    float *xhi, *xlo, *wqh, *wql, *woh, *wol;
    float *qhi, *qlo, *khi, *klo, *vhi, *vlo, *ahi, *alo;
    cudaGetSymbolAddress((void**)&xhi, g_xhi);
    cudaGetSymbolAddress((void**)&xlo, g_xlo);
    cudaGetSymbolAddress((void**)&wqh, g_wqh);
    cudaGetSymbolAddress((void**)&wql, g_wql);
    cudaGetSymbolAddress((void**)&woh, g_woh);
    cudaGetSymbolAddress((void**)&wol, g_wol);
    cudaGetSymbolAddress((void**)&qhi, g_qhi);
    cudaGetSymbolAddress((void**)&qlo, g_qlo);
    cudaGetSymbolAddress((void**)&khi, g_khi);
    cudaGetSymbolAddress((void**)&klo, g_klo);
    cudaGetSymbolAddress((void**)&vhi, g_vhi);
    cudaGetSymbolAddress((void**)&vlo, g_vlo);
    cudaGetSymbolAddress((void**)&ahi, g_ahi);
    cudaGetSymbolAddress((void**)&alo, g_alo);

    cudaFuncSetAttribute(gemm_mma<3 * D_, 1>,
                         cudaFuncAttributeMaxDynamicSharedMemorySize, GEMM_SMEM);
    cudaFuncSetAttribute(gemm_mma<D_, 0>,
                         cudaFuncAttributeMaxDynamicSharedMemorySize, GEMM_SMEM);
    cudaFuncSetAttribute(attn_mma,
                         cudaFuncAttributeMaxDynamicSharedMemorySize, ATTN_SMEM);

    // 0) Split inputs into tf32 hi/lo planes
    split_kernel<<<(int)(NX / 4 + 255) / 256, 256>>>(
        (const float4*)x, (float4*)xhi, (float4*)xlo, (int)(NX / 4));
    split_kernel<<<(int)(NWQ / 4 + 255) / 256, 256>>>(
        (const float4*)w_qkv, (float4*)wqh, (float4*)wql, (int)(NWQ / 4));
    split_kernel<<<(int)(NWO / 4 + 255) / 256, 256>>>(
        (const float4*)w_out, (float4*)woh, (float4*)wol, (int)(NWO / 4));

    // 1) QKV projection -> q/k/v hi-lo planes + raw k/v into d_out
    gemm_mma<3 * D_, 1><<<dim3((3 * D_) / 128, (B_ * L_) / 128), 256, GEMM_SMEM>>>(
        xhi, xlo, wqh, wql, b_qkv,
        qhi, qlo, khi, klo, vhi, vlo, kout, vout);

    // 2) Causal flash attention -> attn-out hi/lo planes
    attn_mma<<<dim3(L_ / 128, B_ * H_), 256, ATTN_SMEM>>>(
        qhi, qlo, khi, klo, vhi, vlo, ahi, alo);

    // 3) Output projection -> d_out
    gemm_mma<D_, 0><<<dim3(D_ / 128, (B_ * L_) / 128), 256, GEMM_SMEM>>>(
        ahi, alo, woh, wol, b_out,
        out, nullptr, nullptr, nullptr, nullptr, nullptr, nullptr, nullptr);
}